// round 12
// baseline (speedup 1.0000x reference)
#include <cuda_runtime.h>

// Dilated attention, fused rates + 2-way i-split K/V loads.
// B=4,H=16,T=8192,D=64. One block (512 thr, 16 warps) per (b,h,64-tok window).
// Warp t owns rows 4t..4t+3. Lane: i=lane>>3, kk=lane&7; ih=i&1, ip=i>>1.
// Score: lane loads K[key k0+8m+kk] 16B sub-chunk (8*dc2+4*ih), partial dots
// for its row PAIR (2ip, 2ip+1); one sel+shfl_xor(8) per m -> lane (i,kk)
// owns score(row i, key 8m+kk) (R11 layout; softmax unchanged).
// PV: lane handles keys 8m+4*ih+j (j<4), V read at d-cols 4kk & 32+4kk,
// accumulates 2 row-partials; one final shfl_xor(8) combine.
//   r1: S=8,  j1=t>>1, active iff j1%2==h%2,        k0=8*j1
//   r2: S=16, j2=t>>2, active iff j2==h%4,          k0=16*j2
//   r3: S=32, j3=t>>3, active iff (2W+j3)%8==h%8,   k0=32*j3
//   r4: S=64, active iff W%16==h%16,                k0=0

#define STRIDE 68   // smem row stride (floats): 68%32=4 -> kk-rows hit distinct bank groups

__device__ __forceinline__ float dot4(float4 a, float4 b) {
    return a.x * b.x + a.y * b.y + a.z * b.z + a.w * b.w;
}

__device__ __forceinline__ void cp16(unsigned int saddr, const float* g) {
    asm volatile("cp.async.cg.shared.global [%0], [%1], 16;\n"
                 :: "r"(saddr), "l"(g));
}

template <int NBP>
__device__ __forceinline__ void seg_multi(
    const float* __restrict__ qs, const float* __restrict__ ks,
    const float* __restrict__ vs, int w_id, int lane, int k0,
    int kA, bool aA, int kB, bool aB, int kC, bool aC, float* acc)
{
    const int i  = lane >> 3;
    const int kk = lane & 7;
    const int ih = i & 1;
    const int qr = (w_id << 2) + i;
    const int r0 = (w_id << 2) + ((i >> 1) << 1);   // pair base row
    const bool hb = (ih != 0);

    // ---- score phase: K split 2-way over ih ----
    float pa[NBP], pb[NBP];
#pragma unroll
    for (int m = 0; m < NBP; m++) { pa[m] = 0.f; pb[m] = 0.f; }

    const float* q0p = qs + r0 * STRIDE + 4 * ih;   // row r0, lane's sub-chunk
    const float* kpp = ks + (k0 + kk) * STRIDE + 4 * ih;
#pragma unroll
    for (int dc2 = 0; dc2 < 8; dc2++) {
        float4 q0 = *reinterpret_cast<const float4*>(q0p + dc2 * 8);
        float4 q1 = *reinterpret_cast<const float4*>(q0p + STRIDE + dc2 * 8);
#pragma unroll
        for (int m = 0; m < NBP; m++) {
            float4 kv = *reinterpret_cast<const float4*>(kpp + m * 8 * STRIDE + dc2 * 8);
            pa[m] += dot4(q0, kv);
            pb[m] += dot4(q1, kv);
        }
    }

    // combine halves: lane keeps its own row (r0+ih), sends partner's row
    float sc[NBP];
#pragma unroll
    for (int m = 0; m < NBP; m++) {
        float x = hb ? pb[m] : pa[m];
        float y = hb ? pa[m] : pb[m];
        sc[m] = x + __shfl_xor_sync(0xffffffffu, y, 8);
    }

    // ---- causal mask + scale ----
#pragma unroll
    for (int m = 0; m < NBP; m++) {
        int key = k0 + 8 * m + kk;
        sc[m] = (key <= qr) ? sc[m] * 0.125f : -1e30f;
    }

    // ---- union softmax: sc[] becomes exponentials; invU = 1/sum ----
    float invU;
    {
        float mx = -1e30f;
#pragma unroll
        for (int m = 0; m < NBP; m++) mx = fmaxf(mx, sc[m]);
        mx = fmaxf(mx, __shfl_xor_sync(0xffffffffu, mx, 1));
        mx = fmaxf(mx, __shfl_xor_sync(0xffffffffu, mx, 2));
        mx = fmaxf(mx, __shfl_xor_sync(0xffffffffu, mx, 4));
        float sum = 0.f;
#pragma unroll
        for (int m = 0; m < NBP; m++) {
            sc[m] = __expf(sc[m] - mx);
            sum += sc[m];
        }
        sum += __shfl_xor_sync(0xffffffffu, sum, 1);
        sum += __shfl_xor_sync(0xffffffffu, sum, 2);
        sum += __shfl_xor_sync(0xffffffffu, sum, 4);
        invU = 1.f / sum;
    }

    // ---- sub-rate inverse sums (shared exponentials) ----
    float invA = 0.f, invB = 0.f, invC = 0.f;
    if (aA) {
        float s = 0.f;
#pragma unroll
        for (int m = 0; m < NBP; m++)
            s += ((k0 + 8 * m + kk) >= kA) ? sc[m] : 0.f;
        s += __shfl_xor_sync(0xffffffffu, s, 1);
        s += __shfl_xor_sync(0xffffffffu, s, 2);
        s += __shfl_xor_sync(0xffffffffu, s, 4);
        invA = 1.f / s;
    }
    if (aB) {
        float s = 0.f;
#pragma unroll
        for (int m = 0; m < NBP; m++)
            s += ((k0 + 8 * m + kk) >= kB) ? sc[m] : 0.f;
        s += __shfl_xor_sync(0xffffffffu, s, 1);
        s += __shfl_xor_sync(0xffffffffu, s, 2);
        s += __shfl_xor_sync(0xffffffffu, s, 4);
        invB = 1.f / s;
    }
    if (aC) {
        float s = 0.f;
#pragma unroll
        for (int m = 0; m < NBP; m++)
            s += ((k0 + 8 * m + kk) >= kC) ? sc[m] : 0.f;
        s += __shfl_xor_sync(0xffffffffu, s, 1);
        s += __shfl_xor_sync(0xffffffffu, s, 2);
        s += __shfl_xor_sync(0xffffffffu, s, 4);
        invC = 1.f / s;
    }

    // combined coefficient in place: sc[m] = summed probs over rates
#pragma unroll
    for (int m = 0; m < NBP; m++) {
        int key = k0 + 8 * m + kk;
        float c = invU;
        c += (aA && key >= kA) ? invA : 0.f;
        c += (aB && key >= kB) ? invB : 0.f;
        c += (aC && key >= kC) ? invC : 0.f;
        sc[m] *= c;
    }

    // ---- PV: V split 2-way over ih; lane handles keys 8m+4*ih+j ----
    float A0[8], A1[8];
#pragma unroll
    for (int j = 0; j < 8; j++) { A0[j] = 0.f; A1[j] = 0.f; }

    const int src0 = (r0 - (w_id << 2)) << 3;       // (2ip)<<3 within warp
    const float* vbase = vs + (k0 + 4 * ih) * STRIDE + (kk << 2);
#pragma unroll
    for (int m = 0; m < NBP; m++) {
#pragma unroll
        for (int j = 0; j < 4; j++) {
            const float* vr = vbase + (8 * m + j) * STRIDE;
            float4 va = *reinterpret_cast<const float4*>(vr);
            float4 vb = *reinterpret_cast<const float4*>(vr + 32);
            const int csub = 4 * ih + j;            // key & 7
            float p0 = __shfl_sync(0xffffffffu, sc[m], src0 | csub);
            float p1 = __shfl_sync(0xffffffffu, sc[m], (src0 + 8) | csub);
            A0[0] += p0 * va.x; A0[1] += p0 * va.y;
            A0[2] += p0 * va.z; A0[3] += p0 * va.w;
            A0[4] += p0 * vb.x; A0[5] += p0 * vb.y;
            A0[6] += p0 * vb.z; A0[7] += p0 * vb.w;
            A1[0] += p1 * va.x; A1[1] += p1 * va.y;
            A1[2] += p1 * va.z; A1[3] += p1 * va.w;
            A1[4] += p1 * vb.x; A1[5] += p1 * vb.y;
            A1[6] += p1 * vb.z; A1[7] += p1 * vb.w;
        }
    }

    // combine key-halves over ih: lane owns row i = r0 + ih
#pragma unroll
    for (int j = 0; j < 8; j++) {
        float x = hb ? A1[j] : A0[j];
        float y = hb ? A0[j] : A1[j];
        acc[j] += x + __shfl_xor_sync(0xffffffffu, y, 8);
    }
}

#define SMEM_KS (64 * STRIDE)
#define SMEM_VS (2 * 64 * STRIDE)
#define SMEM_FLOATS (3 * 64 * STRIDE)
#define SMEM_BYTES  (SMEM_FLOATS * 4)

__global__ void __launch_bounds__(512, 3)
dilated_attn_kernel(const float* __restrict__ Q, const float* __restrict__ K,
                    const float* __restrict__ V, float* __restrict__ out)
{
    extern __shared__ float smem[];
    float* qs = smem;
    float* ks = smem + SMEM_KS;
    float* vs = smem + SMEM_VS;

    const int wWin = blockIdx.x;
    const int h    = blockIdx.y;
    const int b    = blockIdx.z;
    const int tid  = threadIdx.x;
    const int base = ((b * 16 + h) * 8192 + wWin * 64) * 64;

    const bool r4_act = ((wWin & 15) == (h & 15));

    // cooperative tile load via cp.async.cg, skipping never-touched rows
    {
        unsigned int qa = (unsigned int)__cvta_generic_to_shared(qs);
        unsigned int ka = (unsigned int)__cvta_generic_to_shared(ks);
        unsigned int va = (unsigned int)__cvta_generic_to_shared(vs);
#pragma unroll
        for (int it = 0; it < 2; it++) {
            int idx = tid + it * 512;          // 0..1023 float4s
            int row = idx >> 4;
            int col = (idx & 15) << 2;
            bool need = (((row >> 3) & 1) == (h & 1))
                     || ((row >> 4) == (h & 3))
                     || ((((wWin << 1) + (row >> 5)) & 7) == (h & 7))
                     || r4_act;
            if (need) {
                unsigned int so = (unsigned int)(row * STRIDE + col) * 4u;
                int go = base + row * 64 + col;
                cp16(qa + so, Q + go);
                cp16(ka + so, K + go);
                cp16(va + so, V + go);
            }
        }
        asm volatile("cp.async.commit_group;\n");
        asm volatile("cp.async.wait_group 0;\n");
    }
    __syncthreads();

    const int w_id = tid >> 5;   // 0..15
    const int lane = tid & 31;

    float acc[8];
#pragma unroll
    for (int j = 0; j < 8; j++) acc[j] = 0.f;

    // rate activity (warp-uniform)
    const int j1 = w_id >> 1, j2 = w_id >> 2, j3 = w_id >> 3;
    const bool A1 = (j1 & 1) == (h & 1);
    const bool A2 = j2 == (h & 3);
    const bool A3 = ((((wWin << 1) + j3) & 7) == (h & 7));
    const int k1 = j1 << 3, k2 = j2 << 4, k3 = j3 << 5;

    if (r4_act) {
        switch (w_id >> 1) {
            case 0: seg_multi<1>(qs, ks, vs, w_id, lane, 0, k3, A3, k2, A2, k1, A1, acc); break;
            case 1: seg_multi<2>(qs, ks, vs, w_id, lane, 0, k3, A3, k2, A2, k1, A1, acc); break;
            case 2: seg_multi<3>(qs, ks, vs, w_id, lane, 0, k3, A3, k2, A2, k1, A1, acc); break;
            case 3: seg_multi<4>(qs, ks, vs, w_id, lane, 0, k3, A3, k2, A2, k1, A1, acc); break;
            case 4: seg_multi<5>(qs, ks, vs, w_id, lane, 0, k3, A3, k2, A2, k1, A1, acc); break;
            case 5: seg_multi<6>(qs, ks, vs, w_id, lane, 0, k3, A3, k2, A2, k1, A1, acc); break;
            case 6: seg_multi<7>(qs, ks, vs, w_id, lane, 0, k3, A3, k2, A2, k1, A1, acc); break;
            case 7: seg_multi<8>(qs, ks, vs, w_id, lane, 0, k3, A3, k2, A2, k1, A1, acc); break;
        }
    } else if (A3) {
        switch ((w_id & 7) >> 1) {
            case 0: seg_multi<1>(qs, ks, vs, w_id, lane, k3, k2, A2, k1, A1, 0, false, acc); break;
            case 1: seg_multi<2>(qs, ks, vs, w_id, lane, k3, k2, A2, k1, A1, 0, false, acc); break;
            case 2: seg_multi<3>(qs, ks, vs, w_id, lane, k3, k2, A2, k1, A1, 0, false, acc); break;
            case 3: seg_multi<4>(qs, ks, vs, w_id, lane, k3, k2, A2, k1, A1, 0, false, acc); break;
        }
    } else if (A2) {
        if ((w_id & 3) < 2)
            seg_multi<1>(qs, ks, vs, w_id, lane, k2, k1, A1, 0, false, 0, false, acc);
        else
            seg_multi<2>(qs, ks, vs, w_id, lane, k2, k1, A1, 0, false, 0, false, acc);
    } else if (A1) {
        seg_multi<1>(qs, ks, vs, w_id, lane, k1, 0, false, 0, false, 0, false, acc);
    }

    // write (avg over 4 rates); lane (i,kk) owns row i, d {4kk..,32+4kk..}
    const int i  = lane >> 3;
    const int kk = lane & 7;
    const int qr = (w_id << 2) + i;
    float* orow = out + base + qr * 64 + (kk << 2);
    float4 o0, o1;
    o0.x = acc[0] * 0.25f; o0.y = acc[1] * 0.25f;
    o0.z = acc[2] * 0.25f; o0.w = acc[3] * 0.25f;
    o1.x = acc[4] * 0.25f; o1.y = acc[5] * 0.25f;
    o1.z = acc[6] * 0.25f; o1.w = acc[7] * 0.25f;
    *reinterpret_cast<float4*>(orow)      = o0;
    *reinterpret_cast<float4*>(orow + 32) = o1;
}

extern "C" void kernel_launch(void* const* d_in, const int* in_sizes, int n_in,
                              void* d_out, int out_size)
{
    const float* Q = (const float*)d_in[0];
    const float* K = (const float*)d_in[1];
    const float* V = (const float*)d_in[2];
    float* out = (float*)d_out;

    cudaFuncSetAttribute(dilated_attn_kernel,
                         cudaFuncAttributeMaxDynamicSharedMemorySize, SMEM_BYTES);

    dim3 grid(128, 16, 4);
    dilated_attn_kernel<<<grid, 512, SMEM_BYTES>>>(Q, K, V, out);
}

// round 13
// speedup vs baseline: 1.9905x; 1.9905x over previous
#include <cuda_runtime.h>

// Dilated attention, fused over all 4 rates with nested-suffix rate fusion.
// B=4,H=16,T=8192,D=64. One block (512 thr, 16 warps) per (b,h,64-token
// window). Warp t owns rows 4t..4t+3. Lane: i=lane>>3 (row), kk=lane&7.
// Keys for lane: k0+8m+kk. PV d-ownership: lane owns d in [4kk,4kk+4) and
// [32+4kk,32+4kk+4) -> V loads at kk*16B / 128+kk*16B = bank-conflict-free
// (the old [8kk,8kk+8) mapping put kk and kk+4 in the same bank group).
// Scores once over the union range; per-rate inverse sums from shared
// exponentials; one combined coefficient in place.
//   r1: S=8,  j1=t>>1, active iff j1%2==h%2,         k0=8*j1
//   r2: S=16, j2=t>>2, active iff j2==h%4,           k0=16*j2
//   r3: S=32, j3=t>>3, active iff (2W+j3)%8==h%8,    k0=32*j3
//   r4: S=64, active iff W%16==h%16,                 k0=0

#define STRIDE 68   // smem row stride (floats); 68%32=4 -> row-steps land on distinct bank groups

__device__ __forceinline__ float dot4(float4 a, float4 b) {
    return a.x * b.x + a.y * b.y + a.z * b.z + a.w * b.w;
}

__device__ __forceinline__ void cp16(unsigned int saddr, const float* g) {
    asm volatile("cp.async.cg.shared.global [%0], [%1], 16;\n"
                 :: "r"(saddr), "l"(g));
}

template <int NBP>
__device__ __forceinline__ void seg_multi(
    const float* __restrict__ qs, const float* __restrict__ ks,
    const float* __restrict__ vs, int w_id, int lane, int k0,
    int kA, bool aA, int kB, bool aB, int kC, bool aC, float* acc)
{
    const int i  = lane >> 3;
    const int kk = lane & 7;
    const int qr = (w_id << 2) + i;
    const float* qrow  = qs + qr * STRIDE;
    const float* kbase = ks + (k0 + kk) * STRIDE;

    // scores over the union range
    float sc[NBP];
#pragma unroll
    for (int m = 0; m < NBP; m++) sc[m] = 0.f;
#pragma unroll 4
    for (int dc = 0; dc < 16; dc++) {
        float4 qv = *reinterpret_cast<const float4*>(qrow + dc * 4);
#pragma unroll
        for (int m = 0; m < NBP; m++) {
            float4 kv = *reinterpret_cast<const float4*>(kbase + m * 8 * STRIDE + dc * 4);
            sc[m] += dot4(qv, kv);
        }
    }

    // causal mask + scale
#pragma unroll
    for (int m = 0; m < NBP; m++) {
        int key = k0 + 8 * m + kk;
        sc[m] = (key <= qr) ? sc[m] * 0.125f : -1e30f;
    }

    // union softmax: sc[] becomes exponentials; invU = 1/sum
    float invU;
    {
        float mx = -1e30f;
#pragma unroll
        for (int m = 0; m < NBP; m++) mx = fmaxf(mx, sc[m]);
        mx = fmaxf(mx, __shfl_xor_sync(0xffffffffu, mx, 1));
        mx = fmaxf(mx, __shfl_xor_sync(0xffffffffu, mx, 2));
        mx = fmaxf(mx, __shfl_xor_sync(0xffffffffu, mx, 4));
        float sum = 0.f;
#pragma unroll
        for (int m = 0; m < NBP; m++) {
            sc[m] = __expf(sc[m] - mx);
            sum += sc[m];
        }
        sum += __shfl_xor_sync(0xffffffffu, sum, 1);
        sum += __shfl_xor_sync(0xffffffffu, sum, 2);
        sum += __shfl_xor_sync(0xffffffffu, sum, 4);
        invU = 1.f / sum;
    }

    // sub-rate inverse sums from the same exponentials (warp-uniform guards)
    float invA = 0.f, invB = 0.f, invC = 0.f;
    if (aA) {
        float s = 0.f;
#pragma unroll
        for (int m = 0; m < NBP; m++)
            s += ((k0 + 8 * m + kk) >= kA) ? sc[m] : 0.f;
        s += __shfl_xor_sync(0xffffffffu, s, 1);
        s += __shfl_xor_sync(0xffffffffu, s, 2);
        s += __shfl_xor_sync(0xffffffffu, s, 4);
        invA = 1.f / s;
    }
    if (aB) {
        float s = 0.f;
#pragma unroll
        for (int m = 0; m < NBP; m++)
            s += ((k0 + 8 * m + kk) >= kB) ? sc[m] : 0.f;
        s += __shfl_xor_sync(0xffffffffu, s, 1);
        s += __shfl_xor_sync(0xffffffffu, s, 2);
        s += __shfl_xor_sync(0xffffffffu, s, 4);
        invB = 1.f / s;
    }
    if (aC) {
        float s = 0.f;
#pragma unroll
        for (int m = 0; m < NBP; m++)
            s += ((k0 + 8 * m + kk) >= kC) ? sc[m] : 0.f;
        s += __shfl_xor_sync(0xffffffffu, s, 1);
        s += __shfl_xor_sync(0xffffffffu, s, 2);
        s += __shfl_xor_sync(0xffffffffu, s, 4);
        invC = 1.f / s;
    }

    // apply combined coefficient in place
#pragma unroll
    for (int m = 0; m < NBP; m++) {
        int key = k0 + 8 * m + kk;
        float c = invU;
        c += (aA && key >= kA) ? invA : 0.f;
        c += (aB && key >= kB) ? invB : 0.f;
        c += (aC && key >= kC) ? invC : 0.f;
        sc[m] *= c;
    }

    // PV: lane accumulates d [4kk,4kk+4) and [32+4kk,32+4kk+4) of its row.
    // V loads at kk*16B and 128+kk*16B -> conflict-free phases.
    const int srcbase = lane & ~7;
    const float* vbase = vs + k0 * STRIDE + (kk << 2);
#pragma unroll 4
    for (int c = 0; c < NBP * 8; c++) {
        float p = __shfl_sync(0xffffffffu, sc[c >> 3], srcbase | (c & 7));
        const float* vr = vbase + c * STRIDE;
        float4 v0 = *reinterpret_cast<const float4*>(vr);
        float4 v1 = *reinterpret_cast<const float4*>(vr + 32);
        acc[0] += p * v0.x; acc[1] += p * v0.y;
        acc[2] += p * v0.z; acc[3] += p * v0.w;
        acc[4] += p * v1.x; acc[5] += p * v1.y;
        acc[6] += p * v1.z; acc[7] += p * v1.w;
    }
}

#define SMEM_KS (64 * STRIDE)
#define SMEM_VS (2 * 64 * STRIDE)
#define SMEM_FLOATS (3 * 64 * STRIDE)
#define SMEM_BYTES  (SMEM_FLOATS * 4)

__global__ void __launch_bounds__(512, 4)
dilated_attn_kernel(const float* __restrict__ Q, const float* __restrict__ K,
                    const float* __restrict__ V, float* __restrict__ out)
{
    extern __shared__ float smem[];
    float* qs = smem;
    float* ks = smem + SMEM_KS;
    float* vs = smem + SMEM_VS;

    const int wWin = blockIdx.x;
    const int h    = blockIdx.y;
    const int b    = blockIdx.z;
    const int tid  = threadIdx.x;
    const int base = ((b * 16 + h) * 8192 + wWin * 64) * 64;

    const bool r4_act = ((wWin & 15) == (h & 15));

    // cooperative tile load via cp.async.cg, skipping never-touched rows
    {
        unsigned int qa = (unsigned int)__cvta_generic_to_shared(qs);
        unsigned int ka = (unsigned int)__cvta_generic_to_shared(ks);
        unsigned int va = (unsigned int)__cvta_generic_to_shared(vs);
#pragma unroll
        for (int it = 0; it < 2; it++) {
            int idx = tid + it * 512;          // 0..1023 float4s
            int row = idx >> 4;
            int col = (idx & 15) << 2;
            bool need = (((row >> 3) & 1) == (h & 1))
                     || ((row >> 4) == (h & 3))
                     || ((((wWin << 1) + (row >> 5)) & 7) == (h & 7))
                     || r4_act;
            if (need) {
                unsigned int so = (unsigned int)(row * STRIDE + col) * 4u;
                int go = base + row * 64 + col;
                cp16(qa + so, Q + go);
                cp16(ka + so, K + go);
                cp16(va + so, V + go);
            }
        }
        asm volatile("cp.async.commit_group;\n");
        asm volatile("cp.async.wait_group 0;\n");
    }
    __syncthreads();

    const int w_id = tid >> 5;   // 0..15
    const int lane = tid & 31;

    float acc[8];
#pragma unroll
    for (int j = 0; j < 8; j++) acc[j] = 0.f;

    // rate activity (warp-uniform)
    const int j1 = w_id >> 1, j2 = w_id >> 2, j3 = w_id >> 3;
    const bool A1 = (j1 & 1) == (h & 1);
    const bool A2 = j2 == (h & 3);
    const bool A3 = ((((wWin << 1) + j3) & 7) == (h & 7));
    const int k1 = j1 << 3, k2 = j2 << 4, k3 = j3 << 5;

    if (r4_act) {
        switch (w_id >> 1) {
            case 0: seg_multi<1>(qs, ks, vs, w_id, lane, 0, k3, A3, k2, A2, k1, A1, acc); break;
            case 1: seg_multi<2>(qs, ks, vs, w_id, lane, 0, k3, A3, k2, A2, k1, A1, acc); break;
            case 2: seg_multi<3>(qs, ks, vs, w_id, lane, 0, k3, A3, k2, A2, k1, A1, acc); break;
            case 3: seg_multi<4>(qs, ks, vs, w_id, lane, 0, k3, A3, k2, A2, k1, A1, acc); break;
            case 4: seg_multi<5>(qs, ks, vs, w_id, lane, 0, k3, A3, k2, A2, k1, A1, acc); break;
            case 5: seg_multi<6>(qs, ks, vs, w_id, lane, 0, k3, A3, k2, A2, k1, A1, acc); break;
            case 6: seg_multi<7>(qs, ks, vs, w_id, lane, 0, k3, A3, k2, A2, k1, A1, acc); break;
            case 7: seg_multi<8>(qs, ks, vs, w_id, lane, 0, k3, A3, k2, A2, k1, A1, acc); break;
        }
    } else if (A3) {
        switch ((w_id & 7) >> 1) {
            case 0: seg_multi<1>(qs, ks, vs, w_id, lane, k3, k2, A2, k1, A1, 0, false, acc); break;
            case 1: seg_multi<2>(qs, ks, vs, w_id, lane, k3, k2, A2, k1, A1, 0, false, acc); break;
            case 2: seg_multi<3>(qs, ks, vs, w_id, lane, k3, k2, A2, k1, A1, 0, false, acc); break;
            case 3: seg_multi<4>(qs, ks, vs, w_id, lane, k3, k2, A2, k1, A1, 0, false, acc); break;
        }
    } else if (A2) {
        if ((w_id & 3) < 2)
            seg_multi<1>(qs, ks, vs, w_id, lane, k2, k1, A1, 0, false, 0, false, acc);
        else
            seg_multi<2>(qs, ks, vs, w_id, lane, k2, k1, A1, 0, false, 0, false, acc);
    } else if (A1) {
        seg_multi<1>(qs, ks, vs, w_id, lane, k1, 0, false, 0, false, 0, false, acc);
    }

    // write (avg over 4 rates); lane (i,kk) owns row i, d 4kk+{0..3} and 32+4kk+{0..3}
    const int i  = lane >> 3;
    const int kk = lane & 7;
    const int qr = (w_id << 2) + i;
    float* orow = out + base + qr * 64 + (kk << 2);
    float4 o0, o1;
    o0.x = acc[0] * 0.25f; o0.y = acc[1] * 0.25f;
    o0.z = acc[2] * 0.25f; o0.w = acc[3] * 0.25f;
    o1.x = acc[4] * 0.25f; o1.y = acc[5] * 0.25f;
    o1.z = acc[6] * 0.25f; o1.w = acc[7] * 0.25f;
    *reinterpret_cast<float4*>(orow)      = o0;
    *reinterpret_cast<float4*>(orow + 32) = o1;
}

extern "C" void kernel_launch(void* const* d_in, const int* in_sizes, int n_in,
                              void* d_out, int out_size)
{
    const float* Q = (const float*)d_in[0];
    const float* K = (const float*)d_in[1];
    const float* V = (const float*)d_in[2];
    float* out = (float*)d_out;

    cudaFuncSetAttribute(dilated_attn_kernel,
                         cudaFuncAttributeMaxDynamicSharedMemorySize, SMEM_BYTES);

    dim3 grid(128, 16, 4);
    dilated_attn_kernel<<<grid, 512, SMEM_BYTES>>>(Q, K, V, out);
}